// round 2
// baseline (speedup 1.0000x reference)
#include <cuda_runtime.h>

#define HH 128
#define WW 128
#define BB 4
#define CC 128
#define GG 2
#define CG 64
#define KIN 576   // 9*64
#define FG 64
#define NPIX (BB*HH*WW)   // 65536

#define XSTR 533          // per-channel row stride in Xs (odd -> conflict-free)
#define XS_FLOATS (64 * XSTR)            // 34112
#define SW_FLOATS (9 * 64 * 20)          // 11520 (oc padded 18->20 for LDS.128)
#define OFFC_SMEM ((XS_FLOATS + SW_FLOATS) * 4)  // 182528 bytes

// Scratch (static device globals; no runtime allocation)
__device__ float g_off_buf[(size_t)GG * NPIX * 18];        // offsets per group/pixel
__device__ float g_samp_buf[(size_t)GG * NPIX * KIN];      // bilinear-sampled tensor (302MB)

// ---------------------------------------------------------------------------
// Kernel A v2: 3x3 SAME conv producing 18 offset channels per group.
// Block = (g, b, 2 rows). x staged TRANSPOSED (channel-major) in smem,
// weights staged padded so 18 oc read as 4xLDS.128 + LDS.64 broadcasts.
// 128 threads; each thread computes 2 output rows x 18 oc (36 accumulators).
// ---------------------------------------------------------------------------
__global__ void __launch_bounds__(128) offset_conv_v2(
        const float* __restrict__ x,
        const float* __restrict__ off_w,
        const float* __restrict__ off_b) {
    extern __shared__ float sm[];
    float* Xs = sm;                   // [64][XSTR]: rows r=0..3 at r*133, col px+1
    float* sw = sm + XS_FLOATS;       // [9*64][20]

    int bid = blockIdx.x;             // g*256 + b*64 + ypair
    int g   = bid >> 8;
    int rem = bid & 255;
    int b   = rem >> 6;
    int y0  = (rem & 63) << 1;        // first of 2 output rows
    int tid = threadIdx.x;            // 128

    // ---- stage weights, padded to 20 floats per (j,ci) ----
    const float* wsrc = off_w + (size_t)g * 10368;
    for (int i = tid; i < 10368; i += 128) {
        int oc = i % 18;
        int jc = i / 18;
        sw[jc * 20 + oc] = wsrc[i];
    }

    // ---- zero halo columns (stored px index 0 and 129) ----
    for (int i = tid; i < 64 * 4 * 2; i += 128) {
        int ci   = i >> 3;
        int r    = (i >> 1) & 3;
        int cpos = (i & 1) ? 129 : 0;
        Xs[ci * XSTR + r * 133 + cpos] = 0.f;
    }
    // ---- zero out-of-image rows ----
    if (y0 == 0) {
        for (int i = tid; i < 64 * 130; i += 128)
            Xs[(i / 130) * XSTR + (i % 130)] = 0.f;
    }
    if (y0 == HH - 2) {
        for (int i = tid; i < 64 * 130; i += 128)
            Xs[(i / 130) * XSTR + 3 * 133 + (i % 130)] = 0.f;
    }

    // ---- stage x rows y0-1 .. y0+2, transposed to channel-major ----
    // i over 4 rows * 128 px * 16 float4-chunks = 8192
    for (int i = tid; i < 4 * 128 * 16; i += 128) {
        int c4 = i & 15;
        int t  = i >> 4;
        int px = t & 127;             // global xx = px, stored at col px+1
        int r  = t >> 7;              // 0..3, global yy = y0-1+r
        int yy = y0 - 1 + r;
        if (yy < 0 || yy >= HH) continue;
        const float4 v = *(const float4*)(x +
            (((size_t)(b * HH + yy) * WW + px) * CC + g * CG + c4 * 4));
        int base = r * 133 + px + 1;
        Xs[(c4 * 4 + 0) * XSTR + base] = v.x;
        Xs[(c4 * 4 + 1) * XSTR + base] = v.y;
        Xs[(c4 * 4 + 2) * XSTR + base] = v.z;
        Xs[(c4 * 4 + 3) * XSTR + base] = v.w;
    }
    __syncthreads();

    int px = tid;                     // 0..127
    float acc0[18], acc1[18];
#pragma unroll
    for (int oc = 0; oc < 18; oc++) {
        float bv = off_b[g * 18 + oc];
        acc0[oc] = bv; acc1[oc] = bv;
    }

    for (int ci = 0; ci < 64; ci++) {
        const float* xp = Xs + ci * XSTR + px;
        float xv[4][3];
#pragma unroll
        for (int r = 0; r < 4; r++)
#pragma unroll
            for (int k = 0; k < 3; k++)
                xv[r][k] = xp[r * 133 + k];

        const float* wbase = sw + ci * 20;
#pragma unroll
        for (int ky = 0; ky < 3; ky++) {
#pragma unroll
            for (int kx = 0; kx < 3; kx++) {
                const float* w = wbase + (ky * 3 + kx) * (64 * 20);
                float4 w0 = *(const float4*)(w);
                float4 w1 = *(const float4*)(w + 4);
                float4 w2 = *(const float4*)(w + 8);
                float4 w3 = *(const float4*)(w + 12);
                float2 w4 = *(const float2*)(w + 16);
                float a0 = xv[ky][kx];        // output row y0   uses rows ky..ky+... r=ky
                float a1 = xv[ky + 1][kx];    // output row y0+1 uses r=ky+1
                float wv[18] = {w0.x,w0.y,w0.z,w0.w, w1.x,w1.y,w1.z,w1.w,
                                w2.x,w2.y,w2.z,w2.w, w3.x,w3.y,w3.z,w3.w,
                                w4.x,w4.y};
#pragma unroll
                for (int oc = 0; oc < 18; oc++) {
                    acc0[oc] += a0 * wv[oc];
                    acc1[oc] += a1 * wv[oc];
                }
            }
        }
    }

    int m0 = (b * HH + y0) * WW + px;
    float* op0 = g_off_buf + ((size_t)g * NPIX + m0) * 18;
    float* op1 = op0 + (size_t)WW * 18;
#pragma unroll
    for (int oc = 0; oc < 18; oc++) { op0[oc] = acc0[oc]; op1[oc] = acc1[oc]; }
}

// ---------------------------------------------------------------------------
// Kernel B: bilinear sampling. One warp per (g, pixel, tap k); lanes = channels.
// Replicates the reference's clip/floor/weight formulas exactly.
// ---------------------------------------------------------------------------
__global__ void sample_kernel(const float* __restrict__ x) {
    int wid  = (blockIdx.x * blockDim.x + threadIdx.x) >> 5;
    int lane = threadIdx.x & 31;
    int k = wid % 9;
    int t = wid / 9;            // g*NPIX + m
    int m = t & (NPIX - 1);
    int g = t >> 16;            // NPIX = 2^16

    int b    = m >> 14;
    int y    = (m >> 7) & 127;
    int xpix = m & 127;

    const float* offp = g_off_buf + ((size_t)g * NPIX + m) * 18 + 2 * k;
    float ox = offp[0];
    float oy = offp[1];

    float fx = (float)xpix + (float)(k % 3 - 1) + ox;
    float fy = (float)y    + (float)(k / 3 - 1) + oy;
    fx = fminf(fmaxf(fx, 0.f), (float)(WW - 1));
    fy = fminf(fmaxf(fy, 0.f), (float)(HH - 1));

    float x0f = floorf(fx), y0f = floorf(fy);
    float x1f = fminf(x0f + 1.f, (float)(WW - 1));
    float y1f = fminf(y0f + 1.f, (float)(HH - 1));

    float tx  = fx - x0f, ty  = fy - y0f;
    float txc = x1f - fx, tyc = y1f - fy;
    float wa = txc * tyc;
    float wb = txc * ty;
    float wc = tx  * tyc;
    float wd = tx  * ty;

    int x0 = (int)x0f, x1 = (int)x1f, y0 = (int)y0f, y1 = (int)y1f;

    const float* base = x + (size_t)b * HH * WW * CC + g * CG;
    const float* p00 = base + ((size_t)y0 * WW + x0) * CC;
    const float* p10 = base + ((size_t)y1 * WW + x0) * CC;
    const float* p01 = base + ((size_t)y0 * WW + x1) * CC;
    const float* p11 = base + ((size_t)y1 * WW + x1) * CC;

    float* sp = g_samp_buf + ((size_t)g * NPIX + m) * KIN + k * CG;
#pragma unroll
    for (int cc = 0; cc < 2; cc++) {
        int c = lane + cc * 32;
        float v = wa * __ldg(p00 + c) + wb * __ldg(p10 + c)
                + wc * __ldg(p01 + c) + wd * __ldg(p11 + c);
        sp[c] = v;
    }
}

// ---------------------------------------------------------------------------
// Kernel C v2: fused depthwise(3x3) + pointwise GEMM, K=576 -> N=64.
// Block = 128 m x 64 n tile, BK=16, 256 threads, 8x4 per-thread tile.
// A tile (depthwise output) computed on the fly while staging to smem.
// ---------------------------------------------------------------------------
__global__ void __launch_bounds__(256) dwpw_gemm_v2(
        const float* __restrict__ dw_w,
        const float* __restrict__ dw_b,
        const float* __restrict__ pw_w,
        const float* __restrict__ pw_b,
        float* __restrict__ out) {
    __shared__ float As[16][129];
    __shared__ float Bs[16][64];

    int g   = blockIdx.y;
    int m0  = blockIdx.x * 128;      // exactly one image row per block
    int tid = threadIdx.x;           // 256
    int tx  = tid & 15;              // n: 4 each
    int ty  = tid >> 4;              // m: 8 each

    float acc[8][4] = {};

    const int akk = tid & 15;        // A-load: k within tile
    const int amm = tid >> 4;        // A-load: m base (stride 16, 8 each)
    const int bf  = tid & 63;        // B-load: f
    const int bk0 = (tid >> 6) * 4;  // B-load: 4 consecutive kk

    for (int kt = 0; kt < 36; kt++) {
        // ---- stage B tile ----
#pragma unroll
        for (int p = 0; p < 4; p++) {
            int kk = bk0 + p;
            Bs[kk][bf] = pw_w[((size_t)g * KIN + kt * 16 + kk) * FG + bf];
        }

        // ---- stage A tile with fused depthwise ----
        {
            int kc = kt * 16 + akk;
            float bias = dw_b[g * KIN + kc];
            float dwv[9];
#pragma unroll
            for (int j = 0; j < 9; j++)
                dwv[j] = dw_w[((size_t)g * 9 + j) * KIN + kc];

#pragma unroll
            for (int p = 0; p < 8; p++) {
                int mm = amm + p * 16;
                int m  = m0 + mm;
                int y  = (m >> 7) & 127;
                int xx = m & 127;
                float a = bias;
#pragma unroll
                for (int j = 0; j < 9; j++) {
                    int ky = j / 3 - 1;
                    int kx = j % 3 - 1;
                    int yy = y + ky;
                    int xq = xx + kx;
                    if (yy >= 0 && yy < HH && xq >= 0 && xq < WW) {
                        a += dwv[j] *
                             g_samp_buf[((size_t)g * NPIX + m + ky * WW + kx) * KIN + kc];
                    }
                }
                As[akk][mm] = a;
            }
        }
        __syncthreads();

        // ---- 128x64x16 inner product ----
#pragma unroll
        for (int kk = 0; kk < 16; kk++) {
            float av[8], bv[4];
#pragma unroll
            for (int i = 0; i < 8; i++) av[i] = As[kk][ty * 8 + i];
#pragma unroll
            for (int j = 0; j < 4; j++) bv[j] = Bs[kk][tx * 4 + j];
#pragma unroll
            for (int i = 0; i < 8; i++)
#pragma unroll
                for (int j = 0; j < 4; j++)
                    acc[i][j] += av[i] * bv[j];
        }
        __syncthreads();
    }

    // ---- epilogue: bias + interleaved output [m, g*64+f] ----
#pragma unroll
    for (int i = 0; i < 8; i++) {
        int m = m0 + ty * 8 + i;
#pragma unroll
        for (int j = 0; j < 4; j++) {
            int f = tx * 4 + j;
            out[(size_t)m * CC + g * FG + f] = acc[i][j] + pw_b[g * FG + f];
        }
    }
}

// ---------------------------------------------------------------------------
extern "C" void kernel_launch(void* const* d_in, const int* in_sizes, int n_in,
                              void* d_out, int out_size) {
    (void)in_sizes; (void)n_in; (void)out_size;
    const float* x     = (const float*)d_in[0];
    const float* off_w = (const float*)d_in[1];
    const float* off_b = (const float*)d_in[2];
    const float* dw_w  = (const float*)d_in[3];
    const float* dw_b  = (const float*)d_in[4];
    const float* pw_w  = (const float*)d_in[5];
    const float* pw_b  = (const float*)d_in[6];
    float* out = (float*)d_out;

    // opt-in to large dynamic smem (idempotent, non-capturing host call)
    cudaFuncSetAttribute(offset_conv_v2,
                         cudaFuncAttributeMaxDynamicSharedMemorySize, OFFC_SMEM);

    // A: offsets (g * b * 64 row-pairs = 512 blocks)
    offset_conv_v2<<<GG * BB * 64, 128, OFFC_SMEM>>>(x, off_w, off_b);

    // B: bilinear sampling; one warp per (g, pixel, tap)
    long long total_threads = (long long)GG * NPIX * 9 * 32;   // 37,748,736
    int blocks = (int)(total_threads / 256);                   // exact: 147456
    sample_kernel<<<blocks, 256>>>(x);

    // C: fused depthwise + pointwise GEMM
    dim3 grid(NPIX / 128, GG);
    dwpw_gemm_v2<<<grid, 256>>>(dw_w, dw_b, pw_w, pw_b, out);
}

// round 3
// speedup vs baseline: 2.0915x; 2.0915x over previous
#include <cuda_runtime.h>

#define HH 128
#define WW 128
#define BB 4
#define CC 128
#define GG 2
#define CG 64
#define KIN 576   // 9*64
#define FG 64
#define NPIX (BB*HH*WW)   // 65536

#define XSTR 533          // per-channel row stride in Xs (odd -> conflict-free)
#define XS_FLOATS (64 * XSTR)            // 34112
#define SW_FLOATS (9 * 64 * 20)          // 11520 (oc padded 18->20 for LDS.128)
#define OFFC_SMEM ((XS_FLOATS + SW_FLOATS) * 4)  // 182528 bytes

// Scratch (static device globals; no runtime allocation)
__device__ float g_off_buf[(size_t)GG * NPIX * 18];        // offsets per group/pixel
__device__ float g_samp_buf[(size_t)GG * NPIX * KIN];      // bilinear-sampled tensor (302MB)

// ---------------------------------------------------------------------------
// Kernel A v3: 3x3 SAME conv producing 18 offset channels per group.
// Block = (g, b, 2 rows), 256 threads: thread = (row-select, px).
// x staged transposed (channel-major) in smem; weights padded to 20/row.
// ---------------------------------------------------------------------------
__global__ void __launch_bounds__(256) offset_conv_v3(
        const float* __restrict__ x,
        const float* __restrict__ off_w,
        const float* __restrict__ off_b) {
    extern __shared__ float sm[];
    float* Xs = sm;                   // [64][XSTR]: rows r=0..3 at r*133, col px+1
    float* sw = sm + XS_FLOATS;       // [9*64][20]

    int bid = blockIdx.x;             // g*256 + b*64 + ypair
    int g   = bid >> 8;
    int rem = bid & 255;
    int b   = rem >> 6;
    int y0  = (rem & 63) << 1;        // first of 2 output rows
    int tid = threadIdx.x;            // 256

    // ---- stage weights, padded to 20 floats per (j,ci) ----
    const float* wsrc = off_w + (size_t)g * 10368;
    for (int i = tid; i < 10368; i += 256) {
        int oc = i % 18;
        int jc = i / 18;
        sw[jc * 20 + oc] = wsrc[i];
    }

    // ---- zero halo columns (stored px index 0 and 129) ----
    for (int i = tid; i < 64 * 4 * 2; i += 256) {
        int ci   = i >> 3;
        int r    = (i >> 1) & 3;
        int cpos = (i & 1) ? 129 : 0;
        Xs[ci * XSTR + r * 133 + cpos] = 0.f;
    }
    // ---- zero out-of-image rows ----
    if (y0 == 0) {
        for (int i = tid; i < 64 * 130; i += 256)
            Xs[(i / 130) * XSTR + (i % 130)] = 0.f;
    }
    if (y0 == HH - 2) {
        for (int i = tid; i < 64 * 130; i += 256)
            Xs[(i / 130) * XSTR + 3 * 133 + (i % 130)] = 0.f;
    }

    // ---- stage x rows y0-1 .. y0+2, transposed to channel-major ----
    for (int i = tid; i < 4 * 128 * 16; i += 256) {
        int c4 = i & 15;
        int t  = i >> 4;
        int px = t & 127;
        int r  = t >> 7;              // 0..3, global yy = y0-1+r
        int yy = y0 - 1 + r;
        if (yy < 0 || yy >= HH) continue;
        const float4 v = *(const float4*)(x +
            (((size_t)(b * HH + yy) * WW + px) * CC + g * CG + c4 * 4));
        int base = r * 133 + px + 1;
        Xs[(c4 * 4 + 0) * XSTR + base] = v.x;
        Xs[(c4 * 4 + 1) * XSTR + base] = v.y;
        Xs[(c4 * 4 + 2) * XSTR + base] = v.z;
        Xs[(c4 * 4 + 3) * XSTR + base] = v.w;
    }
    __syncthreads();

    int px   = tid & 127;
    int rsel = tid >> 7;              // which of the 2 output rows
    float acc[18];
#pragma unroll
    for (int oc = 0; oc < 18; oc++) acc[oc] = off_b[g * 18 + oc];

    for (int ci = 0; ci < 64; ci++) {
        const float* xp = Xs + ci * XSTR + rsel * 133 + px;
        float xv[3][3];
#pragma unroll
        for (int r = 0; r < 3; r++)
#pragma unroll
            for (int k = 0; k < 3; k++)
                xv[r][k] = xp[r * 133 + k];

        const float* wbase = sw + ci * 20;
#pragma unroll
        for (int ky = 0; ky < 3; ky++) {
#pragma unroll
            for (int kx = 0; kx < 3; kx++) {
                const float* w = wbase + (ky * 3 + kx) * (64 * 20);
                float4 w0 = *(const float4*)(w);
                float4 w1 = *(const float4*)(w + 4);
                float4 w2 = *(const float4*)(w + 8);
                float4 w3 = *(const float4*)(w + 12);
                float2 w4 = *(const float2*)(w + 16);
                float a = xv[ky][kx];
                float wv[18] = {w0.x,w0.y,w0.z,w0.w, w1.x,w1.y,w1.z,w1.w,
                                w2.x,w2.y,w2.z,w2.w, w3.x,w3.y,w3.z,w3.w,
                                w4.x,w4.y};
#pragma unroll
                for (int oc = 0; oc < 18; oc++) acc[oc] += a * wv[oc];
            }
        }
    }

    int m = (b * HH + y0 + rsel) * WW + px;
    float* op = g_off_buf + ((size_t)g * NPIX + m) * 18;
#pragma unroll
    for (int oc = 0; oc < 18; oc++) op[oc] = acc[oc];
}

// ---------------------------------------------------------------------------
// Kernel B: bilinear sampling. One warp per (g, pixel, tap k); lanes = channels.
// ---------------------------------------------------------------------------
__global__ void sample_kernel(const float* __restrict__ x) {
    int wid  = (blockIdx.x * blockDim.x + threadIdx.x) >> 5;
    int lane = threadIdx.x & 31;
    int k = wid % 9;
    int t = wid / 9;            // g*NPIX + m
    int m = t & (NPIX - 1);
    int g = t >> 16;

    int b    = m >> 14;
    int y    = (m >> 7) & 127;
    int xpix = m & 127;

    const float* offp = g_off_buf + ((size_t)g * NPIX + m) * 18 + 2 * k;
    float ox = offp[0];
    float oy = offp[1];

    float fx = (float)xpix + (float)(k % 3 - 1) + ox;
    float fy = (float)y    + (float)(k / 3 - 1) + oy;
    fx = fminf(fmaxf(fx, 0.f), (float)(WW - 1));
    fy = fminf(fmaxf(fy, 0.f), (float)(HH - 1));

    float x0f = floorf(fx), y0f = floorf(fy);
    float x1f = fminf(x0f + 1.f, (float)(WW - 1));
    float y1f = fminf(y0f + 1.f, (float)(HH - 1));

    float tx  = fx - x0f, ty  = fy - y0f;
    float txc = x1f - fx, tyc = y1f - fy;
    float wa = txc * tyc;
    float wb = txc * ty;
    float wc = tx  * tyc;
    float wd = tx  * ty;

    int x0 = (int)x0f, x1 = (int)x1f, y0 = (int)y0f, y1 = (int)y1f;

    const float* base = x + (size_t)b * HH * WW * CC + g * CG;
    const float* p00 = base + ((size_t)y0 * WW + x0) * CC;
    const float* p10 = base + ((size_t)y1 * WW + x0) * CC;
    const float* p01 = base + ((size_t)y0 * WW + x1) * CC;
    const float* p11 = base + ((size_t)y1 * WW + x1) * CC;

    float* sp = g_samp_buf + ((size_t)g * NPIX + m) * KIN + k * CG;
#pragma unroll
    for (int cc = 0; cc < 2; cc++) {
        int c = lane + cc * 32;
        float v = wa * __ldg(p00 + c) + wb * __ldg(p10 + c)
                + wc * __ldg(p01 + c) + wd * __ldg(p11 + c);
        sp[c] = v;
    }
}

// ---------------------------------------------------------------------------
// Kernel C v3: fused depthwise(3x3) + pointwise GEMM, K=576 -> N=64.
// Block = one image row (128 m) x 64 f. Per K-chunk of 16 channels:
//   1) stage the 3 needed s-rows into smem (coalesced, read-once)
//   2) depthwise 3x3 from smem -> As
//   3) 128x64x16 FFMA tile
// ---------------------------------------------------------------------------
__global__ void __launch_bounds__(256, 2) dwpw_gemm_v3(
        const float* __restrict__ dw_w,
        const float* __restrict__ dw_b,
        const float* __restrict__ pw_w,
        const float* __restrict__ pw_b,
        float* __restrict__ out) {
    __shared__ float Ss[3][16][133];   // 3 s-rows x 16 kc x (128 + halo), pad 133
    __shared__ float As[16][129];
    __shared__ float Bs[16][64];

    int g   = blockIdx.y;
    int m0  = blockIdx.x * 128;        // one image row
    int y   = (m0 >> 7) & 127;
    int tid = threadIdx.x;             // 256
    int tx  = tid & 15;                // n: 4 each
    int ty  = tid >> 4;                // m: 8 each

    float acc[8][4] = {};

    const int akk = tid & 15;          // depthwise: kc within tile
    const int amm = tid >> 4;          // depthwise: m base (stride 16, 8 each)
    const int bf  = tid & 63;          // B-load: f
    const int bk0 = (tid >> 6) * 4;    // B-load: 4 consecutive kk

    // zero halo columns of Ss (cols 0 and 129); never rewritten
    if (tid < 96) {
        int r  = tid >> 5;
        int kc = (tid >> 1) & 15;
        Ss[r][kc][(tid & 1) ? 129 : 0] = 0.f;
    }
    __syncthreads();

    const float* gs = g_samp_buf + (size_t)g * NPIX * KIN;

    for (int kt = 0; kt < 36; kt++) {
        // ---- stage Ss (3 rows x 16 kc x 128 px) + Bs ----
#pragma unroll
        for (int p = 0; p < 6; p++) {
            int n   = tid + p * 256;        // < 1536
            int kc4 = n & 3;
            int xx  = (n >> 2) & 127;
            int r   = n >> 9;               // 0..2 -> image row y-1+r
            int yy  = y + r - 1;
            float4 v = make_float4(0.f, 0.f, 0.f, 0.f);
            if (yy >= 0 && yy < HH)
                v = *(const float4*)(gs +
                    (size_t)(m0 + (r - 1) * WW + xx) * KIN + kt * 16 + kc4 * 4);
            Ss[r][kc4 * 4 + 0][xx + 1] = v.x;
            Ss[r][kc4 * 4 + 1][xx + 1] = v.y;
            Ss[r][kc4 * 4 + 2][xx + 1] = v.z;
            Ss[r][kc4 * 4 + 3][xx + 1] = v.w;
        }
#pragma unroll
        for (int p = 0; p < 4; p++) {
            int kk = bk0 + p;
            Bs[kk][bf] = pw_w[((size_t)g * KIN + kt * 16 + kk) * FG + bf];
        }
        __syncthreads();

        // ---- depthwise from smem -> As ----
        {
            int kc = kt * 16 + akk;
            float bias = __ldg(dw_b + g * KIN + kc);
            float dwv[9];
#pragma unroll
            for (int j = 0; j < 9; j++)
                dwv[j] = __ldg(dw_w + ((size_t)g * 9 + j) * KIN + kc);

#pragma unroll
            for (int p = 0; p < 8; p++) {
                int xx = amm + p * 16;      // mm == xx (tile = one image row)
                float a = bias;
#pragma unroll
                for (int jy = 0; jy < 3; jy++)
#pragma unroll
                    for (int jx = 0; jx < 3; jx++)
                        a += dwv[jy * 3 + jx] * Ss[jy][akk][xx + jx];
                As[akk][xx] = a;
            }
        }
        __syncthreads();

        // ---- 128x64x16 inner product ----
#pragma unroll
        for (int kk = 0; kk < 16; kk++) {
            float av[8], bv[4];
#pragma unroll
            for (int i = 0; i < 8; i++) av[i] = As[kk][ty * 8 + i];
#pragma unroll
            for (int j = 0; j < 4; j++) bv[j] = Bs[kk][tx * 4 + j];
#pragma unroll
            for (int i = 0; i < 8; i++)
#pragma unroll
                for (int j = 0; j < 4; j++)
                    acc[i][j] += av[i] * bv[j];
        }
        __syncthreads();
    }

    // ---- epilogue ----
#pragma unroll
    for (int i = 0; i < 8; i++) {
        int m = m0 + ty * 8 + i;
#pragma unroll
        for (int j = 0; j < 4; j++) {
            int f = tx * 4 + j;
            out[(size_t)m * CC + g * FG + f] = acc[i][j] + pw_b[g * FG + f];
        }
    }
}

// ---------------------------------------------------------------------------
extern "C" void kernel_launch(void* const* d_in, const int* in_sizes, int n_in,
                              void* d_out, int out_size) {
    (void)in_sizes; (void)n_in; (void)out_size;
    const float* x     = (const float*)d_in[0];
    const float* off_w = (const float*)d_in[1];
    const float* off_b = (const float*)d_in[2];
    const float* dw_w  = (const float*)d_in[3];
    const float* dw_b  = (const float*)d_in[4];
    const float* pw_w  = (const float*)d_in[5];
    const float* pw_b  = (const float*)d_in[6];
    float* out = (float*)d_out;

    cudaFuncSetAttribute(offset_conv_v3,
                         cudaFuncAttributeMaxDynamicSharedMemorySize, OFFC_SMEM);

    // A: offsets (g * b * 64 row-pairs = 512 blocks)
    offset_conv_v3<<<GG * BB * 64, 256, OFFC_SMEM>>>(x, off_w, off_b);

    // B: bilinear sampling; one warp per (g, pixel, tap)
    long long total_threads = (long long)GG * NPIX * 9 * 32;
    int blocks = (int)(total_threads / 256);                   // 147456
    sample_kernel<<<blocks, 256>>>(x);

    // C: fused depthwise + pointwise GEMM
    dim3 grid(NPIX / 128, GG);
    dwpw_gemm_v3<<<grid, 256>>>(dw_w, dw_b, pw_w, pw_b, out);
}

// round 6
// speedup vs baseline: 2.3674x; 1.1319x over previous
#include <cuda_runtime.h>
#include <cuda_bf16.h>
#include <mma.h>
#include <cstdint>

using namespace nvcuda;

#define HH 128
#define WW 128
#define BB 4
#define CC 128
#define GG 2
#define CG 64
#define KIN 576   // 9*64
#define FG 64
#define NPIX (BB*HH*WW)   // 65536

// ---------------- offset conv smem config (v3, unchanged) ----------------
#define XSTR 533
#define XS_FLOATS (64 * XSTR)
#define SW_FLOATS (9 * 64 * 20)
#define OFFC_SMEM ((XS_FLOATS + SW_FLOATS) * 4)  // 182528 bytes

// ---------------- scratch globals ----------------
__device__ float g_off_buf[(size_t)GG * NPIX * 18];
__device__ float g_samp_buf[(size_t)GG * NPIX * KIN];          // 302MB
__device__ __nv_bfloat16 g_pwh[(size_t)GG * FG * KIN];         // pw hi, [g][f][kin]
__device__ __nv_bfloat16 g_pwl[(size_t)GG * FG * KIN];         // pw lo

// ---------------------------------------------------------------------------
// Kernel A v3 (unchanged): offset conv
// ---------------------------------------------------------------------------
__global__ void __launch_bounds__(256) offset_conv_v3(
        const float* __restrict__ x,
        const float* __restrict__ off_w,
        const float* __restrict__ off_b) {
    extern __shared__ float sm[];
    float* Xs = sm;
    float* sw = sm + XS_FLOATS;

    int bid = blockIdx.x;
    int g   = bid >> 8;
    int rem = bid & 255;
    int b   = rem >> 6;
    int y0  = (rem & 63) << 1;
    int tid = threadIdx.x;

    const float* wsrc = off_w + (size_t)g * 10368;
    for (int i = tid; i < 10368; i += 256) {
        int oc = i % 18;
        int jc = i / 18;
        sw[jc * 20 + oc] = wsrc[i];
    }
    for (int i = tid; i < 64 * 4 * 2; i += 256) {
        int ci   = i >> 3;
        int r    = (i >> 1) & 3;
        int cpos = (i & 1) ? 129 : 0;
        Xs[ci * XSTR + r * 133 + cpos] = 0.f;
    }
    if (y0 == 0) {
        for (int i = tid; i < 64 * 130; i += 256)
            Xs[(i / 130) * XSTR + (i % 130)] = 0.f;
    }
    if (y0 == HH - 2) {
        for (int i = tid; i < 64 * 130; i += 256)
            Xs[(i / 130) * XSTR + 3 * 133 + (i % 130)] = 0.f;
    }
    for (int i = tid; i < 4 * 128 * 16; i += 256) {
        int c4 = i & 15;
        int t  = i >> 4;
        int px = t & 127;
        int r  = t >> 7;
        int yy = y0 - 1 + r;
        if (yy < 0 || yy >= HH) continue;
        const float4 v = *(const float4*)(x +
            (((size_t)(b * HH + yy) * WW + px) * CC + g * CG + c4 * 4));
        int base = r * 133 + px + 1;
        Xs[(c4 * 4 + 0) * XSTR + base] = v.x;
        Xs[(c4 * 4 + 1) * XSTR + base] = v.y;
        Xs[(c4 * 4 + 2) * XSTR + base] = v.z;
        Xs[(c4 * 4 + 3) * XSTR + base] = v.w;
    }
    __syncthreads();

    int px   = tid & 127;
    int rsel = tid >> 7;
    float acc[18];
#pragma unroll
    for (int oc = 0; oc < 18; oc++) acc[oc] = off_b[g * 18 + oc];

    for (int ci = 0; ci < 64; ci++) {
        const float* xp = Xs + ci * XSTR + rsel * 133 + px;
        float xv[3][3];
#pragma unroll
        for (int r = 0; r < 3; r++)
#pragma unroll
            for (int k = 0; k < 3; k++)
                xv[r][k] = xp[r * 133 + k];

        const float* wbase = sw + ci * 20;
#pragma unroll
        for (int ky = 0; ky < 3; ky++) {
#pragma unroll
            for (int kx = 0; kx < 3; kx++) {
                const float* w = wbase + (ky * 3 + kx) * (64 * 20);
                float4 w0 = *(const float4*)(w);
                float4 w1 = *(const float4*)(w + 4);
                float4 w2 = *(const float4*)(w + 8);
                float4 w3 = *(const float4*)(w + 12);
                float2 w4 = *(const float2*)(w + 16);
                float a = xv[ky][kx];
                float wv[18] = {w0.x,w0.y,w0.z,w0.w, w1.x,w1.y,w1.z,w1.w,
                                w2.x,w2.y,w2.z,w2.w, w3.x,w3.y,w3.z,w3.w,
                                w4.x,w4.y};
#pragma unroll
                for (int oc = 0; oc < 18; oc++) acc[oc] += a * wv[oc];
            }
        }
    }

    int m = (b * HH + y0 + rsel) * WW + px;
    float* op = g_off_buf + ((size_t)g * NPIX + m) * 18;
#pragma unroll
    for (int oc = 0; oc < 18; oc++) op[oc] = acc[oc];
}

// ---------------------------------------------------------------------------
// Kernel B: bilinear sampling, float2-vectorized.
// ---------------------------------------------------------------------------
__global__ void sample_kernel(const float* __restrict__ x) {
    int wid  = (blockIdx.x * blockDim.x + threadIdx.x) >> 5;
    int lane = threadIdx.x & 31;
    int k = wid % 9;
    int t = wid / 9;
    int m = t & (NPIX - 1);
    int g = t >> 16;

    int b    = m >> 14;
    int y    = (m >> 7) & 127;
    int xpix = m & 127;

    const float* offp = g_off_buf + ((size_t)g * NPIX + m) * 18 + 2 * k;
    float ox = offp[0];
    float oy = offp[1];

    float fx = (float)xpix + (float)(k % 3 - 1) + ox;
    float fy = (float)y    + (float)(k / 3 - 1) + oy;
    fx = fminf(fmaxf(fx, 0.f), (float)(WW - 1));
    fy = fminf(fmaxf(fy, 0.f), (float)(HH - 1));

    float x0f = floorf(fx), y0f = floorf(fy);
    float x1f = fminf(x0f + 1.f, (float)(WW - 1));
    float y1f = fminf(y0f + 1.f, (float)(HH - 1));

    float tx  = fx - x0f, ty  = fy - y0f;
    float txc = x1f - fx, tyc = y1f - fy;
    float wa = txc * tyc;
    float wb = txc * ty;
    float wc = tx  * tyc;
    float wd = tx  * ty;

    int x0 = (int)x0f, x1 = (int)x1f, y0 = (int)y0f, y1 = (int)y1f;

    const float* base = x + (size_t)b * HH * WW * CC + g * CG;
    const float2* p00 = (const float2*)(base + ((size_t)y0 * WW + x0) * CC) + lane;
    const float2* p10 = (const float2*)(base + ((size_t)y1 * WW + x0) * CC) + lane;
    const float2* p01 = (const float2*)(base + ((size_t)y0 * WW + x1) * CC) + lane;
    const float2* p11 = (const float2*)(base + ((size_t)y1 * WW + x1) * CC) + lane;

    float2 a = __ldg(p00), bb2 = __ldg(p10), c2 = __ldg(p01), d2 = __ldg(p11);
    float2 v;
    v.x = wa * a.x + wb * bb2.x + wc * c2.x + wd * d2.x;
    v.y = wa * a.y + wb * bb2.y + wc * c2.y + wd * d2.y;

    float2* sp = (float2*)(g_samp_buf + ((size_t)g * NPIX + m) * KIN + k * CG) + lane;
    *sp = v;
}

// ---------------------------------------------------------------------------
// Prep: split pw weights into bf16 hi/lo, transposed to [g][f][kin].
// ---------------------------------------------------------------------------
__global__ void pw_split_kernel(const float* __restrict__ pw_w) {
    int idx = blockIdx.x * blockDim.x + threadIdx.x;
    if (idx >= GG * KIN * FG) return;
    int f   = idx & 63;
    int kin = (idx >> 6) % KIN;
    int g   = idx / (KIN * FG);
    float v = pw_w[idx];
    __nv_bfloat16 hi = __float2bfloat16(v);
    __nv_bfloat16 lo = __float2bfloat16(v - __bfloat162float(hi));
    size_t o = ((size_t)g * FG + f) * KIN + kin;
    g_pwh[o] = hi;
    g_pwl[o] = lo;
}

// ---------------------------------------------------------------------------
// Kernel C v5b: fused depthwise + bf16-pair WMMA GEMM (HMMA path, sm_103-safe).
// Block = one image row: M=128, N=64, K=576 in 36 chunks of 16.
// 8 warps = 4(m) x 2(n); warp tile 32x32 = 2x2 wmma m16n16k16 frags.
// C = Ah*Bh + Al*Bh + Ah*Bl   (bf16 pair emulation, fp32 accumulate)
// ---------------------------------------------------------------------------
#define KPAD 24                       // halfword stride of A/B smem rows (48B, mult of 16B)
// byte offsets into dynamic smem
#define SS_F    0                     // [3][16][133] floats = 25536 bytes
#define AH_B    25600
#define AL_B    31744
#define BH_B    37888
#define BL_B    40960
#define GEMM_SMEM_B 44032
#define CPAD 68                       // epilogue float stride (272B, mult of 16B)

__global__ void __launch_bounds__(256) dwpw_wmma(
        const float* __restrict__ dw_w,
        const float* __restrict__ dw_b,
        const float* __restrict__ pw_b,
        float* __restrict__ out) {
    extern __shared__ char smc[];
    float* sm_f = (float*)smc;
    __nv_bfloat16* Ah = (__nv_bfloat16*)(smc + AH_B);
    __nv_bfloat16* Al = (__nv_bfloat16*)(smc + AL_B);
    __nv_bfloat16* Bh = (__nv_bfloat16*)(smc + BH_B);
    __nv_bfloat16* Bl = (__nv_bfloat16*)(smc + BL_B);

    int g   = blockIdx.y;
    int m0  = blockIdx.x * 128;
    int y   = blockIdx.x & 127;
    int tid = threadIdx.x;
    int wid = tid >> 5;

    const int warp_m = wid >> 1;      // 0..3 -> m rows 32*warp_m
    const int warp_n = wid & 1;       // 0..1 -> n cols 32*warp_n

    wmma::fragment<wmma::accumulator, 16, 16, 16, float> acc[2][2];
#pragma unroll
    for (int i = 0; i < 2; i++)
#pragma unroll
        for (int j = 0; j < 2; j++) wmma::fill_fragment(acc[i][j], 0.0f);

    // zero Ss halo columns 0 and 129
    if (tid < 96) {
        int r  = tid >> 5;
        int kc = (tid >> 1) & 15;
        sm_f[SS_F + (r * 16 + kc) * 133 + ((tid & 1) ? 129 : 0)] = 0.f;
    }

    const float* gs = g_samp_buf + (size_t)g * NPIX * KIN;

    const int akk = tid & 15;         // depthwise: kc within chunk
    const int amm = tid >> 4;         // depthwise: m base (8 values, stride 16)
    const int bfr = tid >> 2;         // B stage: f
    const int bq  = tid & 3;          // B stage: 4-halfword quarter

    for (int kt = 0; kt < 36; kt++) {
        // ---- stage Ss: 3 rows x 16 kc x 128 px ----
#pragma unroll
        for (int p = 0; p < 6; p++) {
            int n   = tid + p * 256;        // < 1536
            int kc4 = n & 3;
            int xx  = (n >> 2) & 127;
            int r   = n >> 9;               // 0..2
            int yy  = y + r - 1;
            float4 v = make_float4(0.f, 0.f, 0.f, 0.f);
            if (yy >= 0 && yy < HH)
                v = *(const float4*)(gs +
                    (size_t)(m0 + (r - 1) * WW + xx) * KIN + kt * 16 + kc4 * 4);
            float* d = sm_f + SS_F + (r * 16 + kc4 * 4) * 133 + xx + 1;
            d[0]   = v.x;
            d[133] = v.y;
            d[266] = v.z;
            d[399] = v.w;
        }
        // ---- stage B chunk (hi/lo), coalesced 8B loads ----
        {
            size_t bsrc = ((size_t)g * FG + bfr) * KIN + kt * 16 + bq * 4;
            uint2 vh = *(const uint2*)(g_pwh + bsrc);
            uint2 vl = *(const uint2*)(g_pwl + bsrc);
            *(uint2*)(Bh + bfr * KPAD + bq * 4) = vh;
            *(uint2*)(Bl + bfr * KPAD + bq * 4) = vl;
        }
        __syncthreads();                        // Ss + B ready

        // ---- depthwise from Ss -> bf16 hi/lo A tiles ----
        {
            int kc = kt * 16 + akk;
            float bias = __ldg(dw_b + g * KIN + kc);
            float dwv[9];
#pragma unroll
            for (int j = 0; j < 9; j++)
                dwv[j] = __ldg(dw_w + ((size_t)g * 9 + j) * KIN + kc);

#pragma unroll
            for (int p = 0; p < 8; p++) {
                int xx = amm + p * 16;
                float a = bias;
#pragma unroll
                for (int jy = 0; jy < 3; jy++)
#pragma unroll
                    for (int jx = 0; jx < 3; jx++)
                        a += dwv[jy * 3 + jx] * sm_f[SS_F + (jy * 16 + akk) * 133 + xx + jx];
                __nv_bfloat16 hi = __float2bfloat16(a);
                __nv_bfloat16 lo = __float2bfloat16(a - __bfloat162float(hi));
                Ah[xx * KPAD + akk] = hi;
                Al[xx * KPAD + akk] = lo;
            }
        }
        __syncthreads();                        // A ready

        // ---- WMMA: 2x2 tiles per warp, 3 passes ----
        {
            wmma::fragment<wmma::matrix_a, 16, 16, 16, __nv_bfloat16, wmma::row_major> ah[2], al[2];
            wmma::fragment<wmma::matrix_b, 16, 16, 16, __nv_bfloat16, wmma::col_major> bh[2], bl[2];
#pragma unroll
            for (int i = 0; i < 2; i++) {
                wmma::load_matrix_sync(ah[i], Ah + (warp_m * 32 + i * 16) * KPAD, KPAD);
                wmma::load_matrix_sync(al[i], Al + (warp_m * 32 + i * 16) * KPAD, KPAD);
            }
#pragma unroll
            for (int j = 0; j < 2; j++) {
                wmma::load_matrix_sync(bh[j], Bh + (warp_n * 32 + j * 16) * KPAD, KPAD);
                wmma::load_matrix_sync(bl[j], Bl + (warp_n * 32 + j * 16) * KPAD, KPAD);
            }
#pragma unroll
            for (int i = 0; i < 2; i++)
#pragma unroll
                for (int j = 0; j < 2; j++) {
                    wmma::mma_sync(acc[i][j], ah[i], bh[j], acc[i][j]);
                    wmma::mma_sync(acc[i][j], al[i], bh[j], acc[i][j]);
                    wmma::mma_sync(acc[i][j], ah[i], bl[j], acc[i][j]);
                }
        }
        __syncthreads();                        // protect Ss/A/B for next chunk
    }

    // ---- epilogue: frags -> smem (stride CPAD, WMMA-legal) -> bias + stores ----
    float* Cs = sm_f;                           // [128][CPAD] floats = 34816 B
#pragma unroll
    for (int i = 0; i < 2; i++)
#pragma unroll
        for (int j = 0; j < 2; j++)
            wmma::store_matrix_sync(
                Cs + (warp_m * 32 + i * 16) * CPAD + warp_n * 32 + j * 16,
                acc[i][j], CPAD, wmma::mem_row_major);
    __syncthreads();

    for (int idx = tid; idx < 128 * 64; idx += 256) {
        int m = idx >> 6;
        int f = idx & 63;
        out[(size_t)(m0 + m) * CC + g * FG + f] = Cs[m * CPAD + f] + pw_b[g * FG + f];
    }
}

// ---------------------------------------------------------------------------
extern "C" void kernel_launch(void* const* d_in, const int* in_sizes, int n_in,
                              void* d_out, int out_size) {
    (void)in_sizes; (void)n_in; (void)out_size;
    const float* x     = (const float*)d_in[0];
    const float* off_w = (const float*)d_in[1];
    const float* off_b = (const float*)d_in[2];
    const float* dw_w  = (const float*)d_in[3];
    const float* dw_b  = (const float*)d_in[4];
    const float* pw_w  = (const float*)d_in[5];
    const float* pw_b  = (const float*)d_in[6];
    float* out = (float*)d_out;

    cudaFuncSetAttribute(offset_conv_v3,
                         cudaFuncAttributeMaxDynamicSharedMemorySize, OFFC_SMEM);

    // A: offsets
    offset_conv_v3<<<GG * BB * 64, 256, OFFC_SMEM>>>(x, off_w, off_b);

    // Prep: pw hi/lo split (tiny)
    pw_split_kernel<<<(GG * KIN * FG + 255) / 256, 256>>>(pw_w);

    // B: bilinear sampling
    long long total_threads = (long long)GG * NPIX * 9 * 32;
    int blocks = (int)(total_threads / 256);
    sample_kernel<<<blocks, 256>>>(x);

    // C: fused depthwise + WMMA pointwise
    dim3 grid(NPIX / 128, GG);
    dwpw_wmma<<<grid, 256, GEMM_SMEM_B>>>(dw_w, dw_b, pw_b, out);
}

// round 7
// speedup vs baseline: 2.6455x; 1.1175x over previous
#include <cuda_runtime.h>
#include <cuda_bf16.h>
#include <mma.h>
#include <cstdint>

using namespace nvcuda;

#define HH 128
#define WW 128
#define BB 4
#define CC 128
#define GG 2
#define CG 64
#define KIN 576   // 9*64
#define FG 64
#define NPIX (BB*HH*WW)   // 65536

// ---------------- offset conv smem config (v3, unchanged) ----------------
#define XSTR 533
#define XS_FLOATS (64 * XSTR)
#define SW_FLOATS (9 * 64 * 20)
#define OFFC_SMEM ((XS_FLOATS + SW_FLOATS) * 4)  // 182528 bytes

// ---------------- scratch globals ----------------
__device__ float g_off_buf[(size_t)GG * NPIX * 18];
__device__ float g_samp_buf[(size_t)GG * NPIX * KIN];          // 302MB
__device__ __nv_bfloat16 g_pwh[(size_t)GG * FG * KIN];         // pw hi, [g][f][kin]
__device__ __nv_bfloat16 g_pwl[(size_t)GG * FG * KIN];         // pw lo

// ---------------------------------------------------------------------------
// Kernel A v3 (unchanged): offset conv
// ---------------------------------------------------------------------------
__global__ void __launch_bounds__(256) offset_conv_v3(
        const float* __restrict__ x,
        const float* __restrict__ off_w,
        const float* __restrict__ off_b) {
    extern __shared__ float sm[];
    float* Xs = sm;
    float* sw = sm + XS_FLOATS;

    int bid = blockIdx.x;
    int g   = bid >> 8;
    int rem = bid & 255;
    int b   = rem >> 6;
    int y0  = (rem & 63) << 1;
    int tid = threadIdx.x;

    const float* wsrc = off_w + (size_t)g * 10368;
    for (int i = tid; i < 10368; i += 256) {
        int oc = i % 18;
        int jc = i / 18;
        sw[jc * 20 + oc] = wsrc[i];
    }
    for (int i = tid; i < 64 * 4 * 2; i += 256) {
        int ci   = i >> 3;
        int r    = (i >> 1) & 3;
        int cpos = (i & 1) ? 129 : 0;
        Xs[ci * XSTR + r * 133 + cpos] = 0.f;
    }
    if (y0 == 0) {
        for (int i = tid; i < 64 * 130; i += 256)
            Xs[(i / 130) * XSTR + (i % 130)] = 0.f;
    }
    if (y0 == HH - 2) {
        for (int i = tid; i < 64 * 130; i += 256)
            Xs[(i / 130) * XSTR + 3 * 133 + (i % 130)] = 0.f;
    }
    for (int i = tid; i < 4 * 128 * 16; i += 256) {
        int c4 = i & 15;
        int t  = i >> 4;
        int px = t & 127;
        int r  = t >> 7;
        int yy = y0 - 1 + r;
        if (yy < 0 || yy >= HH) continue;
        const float4 v = *(const float4*)(x +
            (((size_t)(b * HH + yy) * WW + px) * CC + g * CG + c4 * 4));
        int base = r * 133 + px + 1;
        Xs[(c4 * 4 + 0) * XSTR + base] = v.x;
        Xs[(c4 * 4 + 1) * XSTR + base] = v.y;
        Xs[(c4 * 4 + 2) * XSTR + base] = v.z;
        Xs[(c4 * 4 + 3) * XSTR + base] = v.w;
    }
    __syncthreads();

    int px   = tid & 127;
    int rsel = tid >> 7;
    float acc[18];
#pragma unroll
    for (int oc = 0; oc < 18; oc++) acc[oc] = off_b[g * 18 + oc];

    for (int ci = 0; ci < 64; ci++) {
        const float* xp = Xs + ci * XSTR + rsel * 133 + px;
        float xv[3][3];
#pragma unroll
        for (int r = 0; r < 3; r++)
#pragma unroll
            for (int k = 0; k < 3; k++)
                xv[r][k] = xp[r * 133 + k];

        const float* wbase = sw + ci * 20;
#pragma unroll
        for (int ky = 0; ky < 3; ky++) {
#pragma unroll
            for (int kx = 0; kx < 3; kx++) {
                const float* w = wbase + (ky * 3 + kx) * (64 * 20);
                float4 w0 = *(const float4*)(w);
                float4 w1 = *(const float4*)(w + 4);
                float4 w2 = *(const float4*)(w + 8);
                float4 w3 = *(const float4*)(w + 12);
                float2 w4 = *(const float2*)(w + 16);
                float a = xv[ky][kx];
                float wv[18] = {w0.x,w0.y,w0.z,w0.w, w1.x,w1.y,w1.z,w1.w,
                                w2.x,w2.y,w2.z,w2.w, w3.x,w3.y,w3.z,w3.w,
                                w4.x,w4.y};
#pragma unroll
                for (int oc = 0; oc < 18; oc++) acc[oc] += a * wv[oc];
            }
        }
    }

    int m = (b * HH + y0 + rsel) * WW + px;
    float* op = g_off_buf + ((size_t)g * NPIX + m) * 18;
#pragma unroll
    for (int oc = 0; oc < 18; oc++) op[oc] = acc[oc];
}

// ---------------------------------------------------------------------------
// Kernel B: bilinear sampling, float2-vectorized (unchanged).
// ---------------------------------------------------------------------------
__global__ void sample_kernel(const float* __restrict__ x) {
    int wid  = (blockIdx.x * blockDim.x + threadIdx.x) >> 5;
    int lane = threadIdx.x & 31;
    int k = wid % 9;
    int t = wid / 9;
    int m = t & (NPIX - 1);
    int g = t >> 16;

    int b    = m >> 14;
    int y    = (m >> 7) & 127;
    int xpix = m & 127;

    const float* offp = g_off_buf + ((size_t)g * NPIX + m) * 18 + 2 * k;
    float ox = offp[0];
    float oy = offp[1];

    float fx = (float)xpix + (float)(k % 3 - 1) + ox;
    float fy = (float)y    + (float)(k / 3 - 1) + oy;
    fx = fminf(fmaxf(fx, 0.f), (float)(WW - 1));
    fy = fminf(fmaxf(fy, 0.f), (float)(HH - 1));

    float x0f = floorf(fx), y0f = floorf(fy);
    float x1f = fminf(x0f + 1.f, (float)(WW - 1));
    float y1f = fminf(y0f + 1.f, (float)(HH - 1));

    float tx  = fx - x0f, ty  = fy - y0f;
    float txc = x1f - fx, tyc = y1f - fy;
    float wa = txc * tyc;
    float wb = txc * ty;
    float wc = tx  * tyc;
    float wd = tx  * ty;

    int x0 = (int)x0f, x1 = (int)x1f, y0 = (int)y0f, y1 = (int)y1f;

    const float* base = x + (size_t)b * HH * WW * CC + g * CG;
    const float2* p00 = (const float2*)(base + ((size_t)y0 * WW + x0) * CC) + lane;
    const float2* p10 = (const float2*)(base + ((size_t)y1 * WW + x0) * CC) + lane;
    const float2* p01 = (const float2*)(base + ((size_t)y0 * WW + x1) * CC) + lane;
    const float2* p11 = (const float2*)(base + ((size_t)y1 * WW + x1) * CC) + lane;

    float2 a = __ldg(p00), bb2 = __ldg(p10), c2 = __ldg(p01), d2 = __ldg(p11);
    float2 v;
    v.x = wa * a.x + wb * bb2.x + wc * c2.x + wd * d2.x;
    v.y = wa * a.y + wb * bb2.y + wc * c2.y + wd * d2.y;

    float2* sp = (float2*)(g_samp_buf + ((size_t)g * NPIX + m) * KIN + k * CG) + lane;
    *sp = v;
}

// ---------------------------------------------------------------------------
// Prep: split pw weights into bf16 hi/lo, transposed to [g][f][kin].
// ---------------------------------------------------------------------------
__global__ void pw_split_kernel(const float* __restrict__ pw_w) {
    int idx = blockIdx.x * blockDim.x + threadIdx.x;
    if (idx >= GG * KIN * FG) return;
    int f   = idx & 63;
    int kin = (idx >> 6) % KIN;
    int g   = idx / (KIN * FG);
    float v = pw_w[idx];
    __nv_bfloat16 hi = __float2bfloat16(v);
    __nv_bfloat16 lo = __float2bfloat16(v - __bfloat162float(hi));
    size_t o = ((size_t)g * FG + f) * KIN + kin;
    g_pwh[o] = hi;
    g_pwl[o] = lo;
}

// ---------------------------------------------------------------------------
// Kernel C v6: fused depthwise + bf16-pair WMMA GEMM.
//  - consecutive-m depthwise windows (30 LDS/thread/chunk vs 72)
//  - dw weights staged in smem once
//  - double-buffered A/B tiles, 2 barriers per chunk
// ---------------------------------------------------------------------------
#define KPAD 24                       // halfword stride of A/B rows (48B)
#define SS_STR 135                    // Ss row stride in floats (sigma=7 mod 32)
// byte offsets into dynamic smem
#define SS_B    0                     // 3*16*135*4 = 25920
#define ADW_B   26112                 // dw weights [10][576] floats = 23040
#define AH0_B   49152                 // A tiles: 128*24*2 = 6144 each
#define AH1_B   55296
#define AL0_B   61440
#define AL1_B   67584
#define BH0_B   73728                 // B tiles: 64*24*2 = 3072 each
#define BH1_B   76800
#define BL0_B   79872
#define BL1_B   82944
#define GEMM_SMEM_B 86016
#define CPAD 68                       // epilogue float stride (272B)

__global__ void __launch_bounds__(256) dwpw_wmma(
        const float* __restrict__ dw_w,
        const float* __restrict__ dw_b,
        const float* __restrict__ pw_b,
        float* __restrict__ out) {
    extern __shared__ char smc[];
    float* Ss  = (float*)smc;                    // [3][16][SS_STR]
    float* sDw = (float*)(smc + ADW_B);          // [10][576]: rows 0-8 taps, 9 bias

    int g   = blockIdx.y;
    int m0  = blockIdx.x * 128;
    int y   = blockIdx.x & 127;
    int tid = threadIdx.x;
    int wid = tid >> 5;

    const int warp_m = wid >> 1;
    const int warp_n = wid & 1;

    wmma::fragment<wmma::accumulator, 16, 16, 16, float> acc[2][2];
#pragma unroll
    for (int i = 0; i < 2; i++)
#pragma unroll
        for (int j = 0; j < 2; j++) wmma::fill_fragment(acc[i][j], 0.0f);

    // stage dw weights + bias into smem once
    for (int i = tid; i < 9 * KIN; i += 256)
        sDw[i] = dw_w[(size_t)g * 9 * KIN + i];
    for (int i = tid; i < KIN; i += 256)
        sDw[9 * KIN + i] = dw_b[g * KIN + i];

    // zero Ss halo columns (stored cols 0 and 129)
    if (tid < 96) {
        int r  = tid >> 5;
        int kc = (tid >> 1) & 15;
        Ss[(r * 16 + kc) * SS_STR + ((tid & 1) ? 129 : 0)] = 0.f;
    }

    const float* gs = g_samp_buf + (size_t)g * NPIX * KIN;

    // depthwise mapping: thread = (akk, mg-window of 8 consecutive pixels)
    const int akk   = tid & 15;
    const int halfh = (tid >> 4) & 1;
    const int wq    = tid >> 5;
    const int mg    = ((wq >> 1) * 4 + (wq & 1)) + 2 * halfh;  // warp pairs {mg, mg+2}
    const int xx0   = mg * 8;

    const int bfr = tid >> 2;         // B stage: f row
    const int bq  = tid & 3;          // B stage: 4-halfword quarter

    __syncthreads();                  // sDw + halo ready

    for (int kt = 0; kt < 36; kt++) {
        const int buf = kt & 1;
        __nv_bfloat16* Ah = (__nv_bfloat16*)(smc + (buf ? AH1_B : AH0_B));
        __nv_bfloat16* Al = (__nv_bfloat16*)(smc + (buf ? AL1_B : AL0_B));
        __nv_bfloat16* Bh = (__nv_bfloat16*)(smc + (buf ? BH1_B : BH0_B));
        __nv_bfloat16* Bl = (__nv_bfloat16*)(smc + (buf ? BL1_B : BL0_B));

        // ---- stage Ss: 3 rows x 16 kc x 128 px ----
#pragma unroll
        for (int p = 0; p < 6; p++) {
            int n   = tid + p * 256;        // < 1536
            int kc4 = n & 3;
            int xx  = (n >> 2) & 127;
            int r   = n >> 9;               // 0..2
            int yy  = y + r - 1;
            float4 v = make_float4(0.f, 0.f, 0.f, 0.f);
            if (yy >= 0 && yy < HH)
                v = *(const float4*)(gs +
                    (size_t)(m0 + (r - 1) * WW + xx) * KIN + kt * 16 + kc4 * 4);
            float* d = Ss + (r * 16 + kc4 * 4) * SS_STR + xx + 1;
            d[0]          = v.x;
            d[SS_STR]     = v.y;
            d[2 * SS_STR] = v.z;
            d[3 * SS_STR] = v.w;
        }
        // ---- stage B chunk (hi/lo) into buf ----
        {
            size_t bsrc = ((size_t)g * FG + bfr) * KIN + kt * 16 + bq * 4;
            uint2 vh = *(const uint2*)(g_pwh + bsrc);
            uint2 vl = *(const uint2*)(g_pwl + bsrc);
            *(uint2*)(Bh + bfr * KPAD + bq * 4) = vh;
            *(uint2*)(Bl + bfr * KPAD + bq * 4) = vl;
        }
        __syncthreads();        // Ss+B ready; all warps past mma(kt-1) -> A[buf] free

        // ---- depthwise: 8 consecutive pixels per thread ----
        {
            int kc = kt * 16 + akk;
            float bias = sDw[9 * KIN + kc];
            float a[8];
#pragma unroll
            for (int i = 0; i < 8; i++) a[i] = bias;
#pragma unroll
            for (int jy = 0; jy < 3; jy++) {
                const float* rp = Ss + (jy * 16 + akk) * SS_STR + xx0;
                float w[10];
#pragma unroll
                for (int q = 0; q < 10; q++) w[q] = rp[q];
                float d0 = sDw[(jy * 3 + 0) * KIN + kc];
                float d1 = sDw[(jy * 3 + 1) * KIN + kc];
                float d2 = sDw[(jy * 3 + 2) * KIN + kc];
#pragma unroll
                for (int i = 0; i < 8; i++)
                    a[i] += d0 * w[i] + d1 * w[i + 1] + d2 * w[i + 2];
            }
#pragma unroll
            for (int i = 0; i < 8; i++) {
                float v = a[i];
                __nv_bfloat16 hi = __float2bfloat16(v);
                __nv_bfloat16 lo = __float2bfloat16(v - __bfloat162float(hi));
                Ah[(xx0 + i) * KPAD + akk] = hi;
                Al[(xx0 + i) * KPAD + akk] = lo;
            }
        }
        __syncthreads();        // A ready; Ss free for next stage

        // ---- WMMA: 2x2 tiles per warp, 3 passes ----
        {
            wmma::fragment<wmma::matrix_a, 16, 16, 16, __nv_bfloat16, wmma::row_major> ah[2], al[2];
            wmma::fragment<wmma::matrix_b, 16, 16, 16, __nv_bfloat16, wmma::col_major> bh[2], bl[2];
#pragma unroll
            for (int i = 0; i < 2; i++) {
                wmma::load_matrix_sync(ah[i], Ah + (warp_m * 32 + i * 16) * KPAD, KPAD);
                wmma::load_matrix_sync(al[i], Al + (warp_m * 32 + i * 16) * KPAD, KPAD);
            }
#pragma unroll
            for (int j = 0; j < 2; j++) {
                wmma::load_matrix_sync(bh[j], Bh + (warp_n * 32 + j * 16) * KPAD, KPAD);
                wmma::load_matrix_sync(bl[j], Bl + (warp_n * 32 + j * 16) * KPAD, KPAD);
            }
#pragma unroll
            for (int i = 0; i < 2; i++)
#pragma unroll
                for (int j = 0; j < 2; j++) {
                    wmma::mma_sync(acc[i][j], ah[i], bh[j], acc[i][j]);
                    wmma::mma_sync(acc[i][j], al[i], bh[j], acc[i][j]);
                    wmma::mma_sync(acc[i][j], ah[i], bl[j], acc[i][j]);
                }
        }
        // no barrier here: next-iter sync1 covers the A/B buffer swap
    }

    __syncthreads();                             // all MMA done before Cs overwrite
    // ---- epilogue: frags -> smem (stride CPAD) -> bias + coalesced stores ----
    float* Cs = (float*)smc;                     // [128][CPAD]
#pragma unroll
    for (int i = 0; i < 2; i++)
#pragma unroll
        for (int j = 0; j < 2; j++)
            wmma::store_matrix_sync(
                Cs + (warp_m * 32 + i * 16) * CPAD + warp_n * 32 + j * 16,
                acc[i][j], CPAD, wmma::mem_row_major);
    __syncthreads();

    for (int idx = tid; idx < 128 * 64; idx += 256) {
        int m = idx >> 6;
        int f = idx & 63;
        out[(size_t)(m0 + m) * CC + g * FG + f] = Cs[m * CPAD + f] + pw_b[g * FG + f];
    }
}

// ---------------------------------------------------------------------------
extern "C" void kernel_launch(void* const* d_in, const int* in_sizes, int n_in,
                              void* d_out, int out_size) {
    (void)in_sizes; (void)n_in; (void)out_size;
    const float* x     = (const float*)d_in[0];
    const float* off_w = (const float*)d_in[1];
    const float* off_b = (const float*)d_in[2];
    const float* dw_w  = (const float*)d_in[3];
    const float* dw_b  = (const float*)d_in[4];
    const float* pw_w  = (const float*)d_in[5];
    const float* pw_b  = (const float*)d_in[6];
    float* out = (float*)d_out;

    cudaFuncSetAttribute(offset_conv_v3,
                         cudaFuncAttributeMaxDynamicSharedMemorySize, OFFC_SMEM);
    cudaFuncSetAttribute(dwpw_wmma,
                         cudaFuncAttributeMaxDynamicSharedMemorySize, GEMM_SMEM_B);

    // A: offsets
    offset_conv_v3<<<GG * BB * 64, 256, OFFC_SMEM>>>(x, off_w, off_b);

    // Prep: pw hi/lo split (tiny)
    pw_split_kernel<<<(GG * KIN * FG + 255) / 256, 256>>>(pw_w);

    // B: bilinear sampling
    long long total_threads = (long long)GG * NPIX * 9 * 32;
    int blocks = (int)(total_threads / 256);
    sample_kernel<<<blocks, 256>>>(x);

    // C: fused depthwise + WMMA pointwise
    dim3 grid(NPIX / 128, GG);
    dwpw_wmma<<<grid, 256, GEMM_SMEM_B>>>(dw_w, dw_b, pw_b, out);
}

// round 8
// speedup vs baseline: 2.7047x; 1.0224x over previous
#include <cuda_runtime.h>
#include <cuda_bf16.h>
#include <mma.h>
#include <cstdint>

using namespace nvcuda;

#define HH 128
#define WW 128
#define BB 4
#define CC 128
#define GG 2
#define CG 64
#define KIN 576   // 9*64
#define FG 64
#define NPIX (BB*HH*WW)   // 65536

// ---------------- offset conv smem config (v3, unchanged) ----------------
#define XSTR 533
#define XS_FLOATS (64 * XSTR)
#define SW_FLOATS (9 * 64 * 20)
#define OFFC_SMEM ((XS_FLOATS + SW_FLOATS) * 4)  // 182528 bytes

// ---------------- scratch globals ----------------
__device__ float g_off_buf[(size_t)GG * NPIX * 18];
__device__ float g_samp_buf[(size_t)GG * NPIX * KIN];          // 302MB
__device__ __nv_bfloat16 g_pwh[(size_t)GG * FG * KIN];         // pw hi, [g][f][kin]
__device__ __nv_bfloat16 g_pwl[(size_t)GG * FG * KIN];         // pw lo

// ---------------------------------------------------------------------------
// Kernel A v3 (unchanged): offset conv
// ---------------------------------------------------------------------------
__global__ void __launch_bounds__(256) offset_conv_v3(
        const float* __restrict__ x,
        const float* __restrict__ off_w,
        const float* __restrict__ off_b) {
    extern __shared__ float sm[];
    float* Xs = sm;
    float* sw = sm + XS_FLOATS;

    int bid = blockIdx.x;
    int g   = bid >> 8;
    int rem = bid & 255;
    int b   = rem >> 6;
    int y0  = (rem & 63) << 1;
    int tid = threadIdx.x;

    const float* wsrc = off_w + (size_t)g * 10368;
    for (int i = tid; i < 10368; i += 256) {
        int oc = i % 18;
        int jc = i / 18;
        sw[jc * 20 + oc] = wsrc[i];
    }
    for (int i = tid; i < 64 * 4 * 2; i += 256) {
        int ci   = i >> 3;
        int r    = (i >> 1) & 3;
        int cpos = (i & 1) ? 129 : 0;
        Xs[ci * XSTR + r * 133 + cpos] = 0.f;
    }
    if (y0 == 0) {
        for (int i = tid; i < 64 * 130; i += 256)
            Xs[(i / 130) * XSTR + (i % 130)] = 0.f;
    }
    if (y0 == HH - 2) {
        for (int i = tid; i < 64 * 130; i += 256)
            Xs[(i / 130) * XSTR + 3 * 133 + (i % 130)] = 0.f;
    }
    for (int i = tid; i < 4 * 128 * 16; i += 256) {
        int c4 = i & 15;
        int t  = i >> 4;
        int px = t & 127;
        int r  = t >> 7;
        int yy = y0 - 1 + r;
        if (yy < 0 || yy >= HH) continue;
        const float4 v = *(const float4*)(x +
            (((size_t)(b * HH + yy) * WW + px) * CC + g * CG + c4 * 4));
        int base = r * 133 + px + 1;
        Xs[(c4 * 4 + 0) * XSTR + base] = v.x;
        Xs[(c4 * 4 + 1) * XSTR + base] = v.y;
        Xs[(c4 * 4 + 2) * XSTR + base] = v.z;
        Xs[(c4 * 4 + 3) * XSTR + base] = v.w;
    }
    __syncthreads();

    int px   = tid & 127;
    int rsel = tid >> 7;
    float acc[18];
#pragma unroll
    for (int oc = 0; oc < 18; oc++) acc[oc] = off_b[g * 18 + oc];

    for (int ci = 0; ci < 64; ci++) {
        const float* xp = Xs + ci * XSTR + rsel * 133 + px;
        float xv[3][3];
#pragma unroll
        for (int r = 0; r < 3; r++)
#pragma unroll
            for (int k = 0; k < 3; k++)
                xv[r][k] = xp[r * 133 + k];

        const float* wbase = sw + ci * 20;
#pragma unroll
        for (int ky = 0; ky < 3; ky++) {
#pragma unroll
            for (int kx = 0; kx < 3; kx++) {
                const float* w = wbase + (ky * 3 + kx) * (64 * 20);
                float4 w0 = *(const float4*)(w);
                float4 w1 = *(const float4*)(w + 4);
                float4 w2 = *(const float4*)(w + 8);
                float4 w3 = *(const float4*)(w + 12);
                float2 w4 = *(const float2*)(w + 16);
                float a = xv[ky][kx];
                float wv[18] = {w0.x,w0.y,w0.z,w0.w, w1.x,w1.y,w1.z,w1.w,
                                w2.x,w2.y,w2.z,w2.w, w3.x,w3.y,w3.z,w3.w,
                                w4.x,w4.y};
#pragma unroll
                for (int oc = 0; oc < 18; oc++) acc[oc] += a * wv[oc];
            }
        }
    }

    int m = (b * HH + y0 + rsel) * WW + px;
    float* op = g_off_buf + ((size_t)g * NPIX + m) * 18;
#pragma unroll
    for (int oc = 0; oc < 18; oc++) op[oc] = acc[oc];
}

// ---------------------------------------------------------------------------
// Kernel B: bilinear sampling, float2-vectorized (unchanged).
// ---------------------------------------------------------------------------
__global__ void sample_kernel(const float* __restrict__ x) {
    int wid  = (blockIdx.x * blockDim.x + threadIdx.x) >> 5;
    int lane = threadIdx.x & 31;
    int k = wid % 9;
    int t = wid / 9;
    int m = t & (NPIX - 1);
    int g = t >> 16;

    int b    = m >> 14;
    int y    = (m >> 7) & 127;
    int xpix = m & 127;

    const float* offp = g_off_buf + ((size_t)g * NPIX + m) * 18 + 2 * k;
    float ox = offp[0];
    float oy = offp[1];

    float fx = (float)xpix + (float)(k % 3 - 1) + ox;
    float fy = (float)y    + (float)(k / 3 - 1) + oy;
    fx = fminf(fmaxf(fx, 0.f), (float)(WW - 1));
    fy = fminf(fmaxf(fy, 0.f), (float)(HH - 1));

    float x0f = floorf(fx), y0f = floorf(fy);
    float x1f = fminf(x0f + 1.f, (float)(WW - 1));
    float y1f = fminf(y0f + 1.f, (float)(HH - 1));

    float tx  = fx - x0f, ty  = fy - y0f;
    float txc = x1f - fx, tyc = y1f - fy;
    float wa = txc * tyc;
    float wb = txc * ty;
    float wc = tx  * tyc;
    float wd = tx  * ty;

    int x0 = (int)x0f, x1 = (int)x1f, y0 = (int)y0f, y1 = (int)y1f;

    const float* base = x + (size_t)b * HH * WW * CC + g * CG;
    const float2* p00 = (const float2*)(base + ((size_t)y0 * WW + x0) * CC) + lane;
    const float2* p10 = (const float2*)(base + ((size_t)y1 * WW + x0) * CC) + lane;
    const float2* p01 = (const float2*)(base + ((size_t)y0 * WW + x1) * CC) + lane;
    const float2* p11 = (const float2*)(base + ((size_t)y1 * WW + x1) * CC) + lane;

    float2 a = __ldg(p00), bb2 = __ldg(p10), c2 = __ldg(p01), d2 = __ldg(p11);
    float2 v;
    v.x = wa * a.x + wb * bb2.x + wc * c2.x + wd * d2.x;
    v.y = wa * a.y + wb * bb2.y + wc * c2.y + wd * d2.y;

    float2* sp = (float2*)(g_samp_buf + ((size_t)g * NPIX + m) * KIN + k * CG) + lane;
    *sp = v;
}

// ---------------------------------------------------------------------------
// Prep: split pw weights into bf16 hi/lo, transposed to [g][f][kin].
// ---------------------------------------------------------------------------
__global__ void pw_split_kernel(const float* __restrict__ pw_w) {
    int idx = blockIdx.x * blockDim.x + threadIdx.x;
    if (idx >= GG * KIN * FG) return;
    int f   = idx & 63;
    int kin = (idx >> 6) % KIN;
    int g   = idx / (KIN * FG);
    float v = pw_w[idx];
    __nv_bfloat16 hi = __float2bfloat16(v);
    __nv_bfloat16 lo = __float2bfloat16(v - __bfloat162float(hi));
    size_t o = ((size_t)g * FG + f) * KIN + kin;
    g_pwh[o] = hi;
    g_pwl[o] = lo;
}

// ---------------------------------------------------------------------------
// Kernel C v7: fused depthwise + bf16-pair WMMA GEMM.
//  - vectorized depthwise window reads (3 LDS vs 30): SS_STR=140, px at px+5
//  - dw weights via __ldg broadcasts (smem freed -> 3 CTAs/SM)
//  - double-buffered A/B tiles, 2 barriers per chunk
// ---------------------------------------------------------------------------
#define KPAD 24                       // halfword stride of A/B rows (48B)
#define SS_STR 140                    // float stride: 140%32=12 -> conflict-free LDS.128
// byte offsets into dynamic smem
#define AH0_B   26880                 // Ss = 3*16*140*4 = 26880 bytes at offset 0
#define AH1_B   33024
#define AL0_B   39168
#define AL1_B   45312
#define BH0_B   51456
#define BH1_B   54528
#define BL0_B   57600
#define BL1_B   60672
#define GEMM_SMEM_B 63744
#define CPAD 68                       // epilogue float stride (272B)

__global__ void __launch_bounds__(256) dwpw_wmma(
        const float* __restrict__ dw_w,
        const float* __restrict__ dw_b,
        const float* __restrict__ pw_b,
        float* __restrict__ out) {
    extern __shared__ char smc[];
    float* Ss = (float*)smc;                     // [3*16][SS_STR], px at px+5

    int g   = blockIdx.y;
    int m0  = blockIdx.x * 128;
    int y   = blockIdx.x & 127;
    int tid = threadIdx.x;
    int wid = tid >> 5;

    const int warp_m = wid >> 1;
    const int warp_n = wid & 1;

    wmma::fragment<wmma::accumulator, 16, 16, 16, float> acc[2][2];
#pragma unroll
    for (int i = 0; i < 2; i++)
#pragma unroll
        for (int j = 0; j < 2; j++) wmma::fill_fragment(acc[i][j], 0.0f);

    // zero Ss halo columns (stored cols 4 and 133) for all 48 rows
    if (tid < 96) {
        int row = tid >> 1;
        Ss[row * SS_STR + ((tid & 1) ? 133 : 4)] = 0.f;
    }

    const float* gs = g_samp_buf + (size_t)g * NPIX * KIN;
    const float* dwp = dw_w + (size_t)g * 9 * KIN;

    // depthwise mapping: thread = (akk, window of 8 consecutive pixels)
    const int akk   = tid & 15;
    const int halfh = (tid >> 4) & 1;
    const int wq    = tid >> 5;
    const int mg    = ((wq >> 1) * 4 + (wq & 1)) + 2 * halfh;
    const int xx0   = mg * 8;

    const int bfr = tid >> 2;         // B stage: f row
    const int bq  = tid & 3;          // B stage: 4-halfword quarter

    __syncthreads();                  // halo ready

    for (int kt = 0; kt < 36; kt++) {
        const int buf = kt & 1;
        __nv_bfloat16* Ah = (__nv_bfloat16*)(smc + (buf ? AH1_B : AH0_B));
        __nv_bfloat16* Al = (__nv_bfloat16*)(smc + (buf ? AL1_B : AL0_B));
        __nv_bfloat16* Bh = (__nv_bfloat16*)(smc + (buf ? BH1_B : BH0_B));
        __nv_bfloat16* Bl = (__nv_bfloat16*)(smc + (buf ? BL1_B : BL0_B));

        // ---- stage Ss: 3 rows x 16 kc x 128 px ----
#pragma unroll
        for (int p = 0; p < 6; p++) {
            int n   = tid + p * 256;        // < 1536
            int kc4 = n & 3;
            int xx  = (n >> 2) & 127;
            int r   = n >> 9;               // 0..2
            int yy  = y + r - 1;
            float4 v = make_float4(0.f, 0.f, 0.f, 0.f);
            if (yy >= 0 && yy < HH)
                v = *(const float4*)(gs +
                    (size_t)(m0 + (r - 1) * WW + xx) * KIN + kt * 16 + kc4 * 4);
            float* d = Ss + (r * 16 + kc4 * 4) * SS_STR + xx + 5;
            d[0]          = v.x;
            d[SS_STR]     = v.y;
            d[2 * SS_STR] = v.z;
            d[3 * SS_STR] = v.w;
        }
        // ---- stage B chunk (hi/lo) into buf ----
        {
            size_t bsrc = ((size_t)g * FG + bfr) * KIN + kt * 16 + bq * 4;
            uint2 vh = *(const uint2*)(g_pwh + bsrc);
            uint2 vl = *(const uint2*)(g_pwl + bsrc);
            *(uint2*)(Bh + bfr * KPAD + bq * 4) = vh;
            *(uint2*)(Bl + bfr * KPAD + bq * 4) = vl;
        }
        __syncthreads();        // Ss+B ready; all warps past mma(kt-1) -> A[buf] free

        // ---- depthwise: 8 consecutive pixels, vectorized window reads ----
        {
            int kc = kt * 16 + akk;
            float bias = __ldg(dw_b + g * KIN + kc);
            float a[8];
#pragma unroll
            for (int i = 0; i < 8; i++) a[i] = bias;
#pragma unroll
            for (int jy = 0; jy < 3; jy++) {
                const float* rp = Ss + (jy * 16 + akk) * SS_STR + xx0 + 4;  // 16B-aligned
                float4 w03 = *(const float4*)(rp);
                float4 w47 = *(const float4*)(rp + 4);
                float2 w89 = *(const float2*)(rp + 8);
                float w[10] = {w03.x, w03.y, w03.z, w03.w,
                               w47.x, w47.y, w47.z, w47.w, w89.x, w89.y};
                float d0 = __ldg(dwp + (jy * 3 + 0) * KIN + kc);
                float d1 = __ldg(dwp + (jy * 3 + 1) * KIN + kc);
                float d2 = __ldg(dwp + (jy * 3 + 2) * KIN + kc);
#pragma unroll
                for (int i = 0; i < 8; i++)
                    a[i] += d0 * w[i] + d1 * w[i + 1] + d2 * w[i + 2];
            }
#pragma unroll
            for (int i = 0; i < 8; i++) {
                float v = a[i];
                __nv_bfloat16 hi = __float2bfloat16(v);
                __nv_bfloat16 lo = __float2bfloat16(v - __bfloat162float(hi));
                Ah[(xx0 + i) * KPAD + akk] = hi;
                Al[(xx0 + i) * KPAD + akk] = lo;
            }
        }
        __syncthreads();        // A ready; Ss free for next stage

        // ---- WMMA: 2x2 tiles per warp, 3 passes ----
        {
            wmma::fragment<wmma::matrix_a, 16, 16, 16, __nv_bfloat16, wmma::row_major> ah[2], al[2];
            wmma::fragment<wmma::matrix_b, 16, 16, 16, __nv_bfloat16, wmma::col_major> bh[2], bl[2];
#pragma unroll
            for (int i = 0; i < 2; i++) {
                wmma::load_matrix_sync(ah[i], Ah + (warp_m * 32 + i * 16) * KPAD, KPAD);
                wmma::load_matrix_sync(al[i], Al + (warp_m * 32 + i * 16) * KPAD, KPAD);
            }
#pragma unroll
            for (int j = 0; j < 2; j++) {
                wmma::load_matrix_sync(bh[j], Bh + (warp_n * 32 + j * 16) * KPAD, KPAD);
                wmma::load_matrix_sync(bl[j], Bl + (warp_n * 32 + j * 16) * KPAD, KPAD);
            }
#pragma unroll
            for (int i = 0; i < 2; i++)
#pragma unroll
                for (int j = 0; j < 2; j++) {
                    wmma::mma_sync(acc[i][j], ah[i], bh[j], acc[i][j]);
                    wmma::mma_sync(acc[i][j], al[i], bh[j], acc[i][j]);
                    wmma::mma_sync(acc[i][j], ah[i], bl[j], acc[i][j]);
                }
        }
        // no barrier: next-iter sync covers the buffer swap
    }

    __syncthreads();                             // all MMA done before Cs overwrite
    // ---- epilogue: frags -> smem (stride CPAD) -> bias + coalesced stores ----
    float* Cs = (float*)smc;                     // [128][CPAD]
#pragma unroll
    for (int i = 0; i < 2; i++)
#pragma unroll
        for (int j = 0; j < 2; j++)
            wmma::store_matrix_sync(
                Cs + (warp_m * 32 + i * 16) * CPAD + warp_n * 32 + j * 16,
                acc[i][j], CPAD, wmma::mem_row_major);
    __syncthreads();

    for (int idx = tid; idx < 128 * 64; idx += 256) {
        int m = idx >> 6;
        int f = idx & 63;
        out[(size_t)(m0 + m) * CC + g * FG + f] = Cs[m * CPAD + f] + pw_b[g * FG + f];
    }
}

// ---------------------------------------------------------------------------
extern "C" void kernel_launch(void* const* d_in, const int* in_sizes, int n_in,
                              void* d_out, int out_size) {
    (void)in_sizes; (void)n_in; (void)out_size;
    const float* x     = (const float*)d_in[0];
    const float* off_w = (const float*)d_in[1];
    const float* off_b = (const float*)d_in[2];
    const float* dw_w  = (const float*)d_in[3];
    const float* dw_b  = (const float*)d_in[4];
    const float* pw_w  = (const float*)d_in[5];
    const float* pw_b  = (const float*)d_in[6];
    float* out = (float*)d_out;

    cudaFuncSetAttribute(offset_conv_v3,
                         cudaFuncAttributeMaxDynamicSharedMemorySize, OFFC_SMEM);
    cudaFuncSetAttribute(dwpw_wmma,
                         cudaFuncAttributeMaxDynamicSharedMemorySize, GEMM_SMEM_B);

    // A: offsets
    offset_conv_v3<<<GG * BB * 64, 256, OFFC_SMEM>>>(x, off_w, off_b);

    // Prep: pw hi/lo split (tiny)
    pw_split_kernel<<<(GG * KIN * FG + 255) / 256, 256>>>(pw_w);

    // B: bilinear sampling
    long long total_threads = (long long)GG * NPIX * 9 * 32;
    int blocks = (int)(total_threads / 256);
    sample_kernel<<<blocks, 256>>>(x);

    // C: fused depthwise + WMMA pointwise
    dim3 grid(NPIX / 128, GG);
    dwpw_wmma<<<grid, 256, GEMM_SMEM_B>>>(dw_w, dw_b, pw_b, out);
}